// round 4
// baseline (speedup 1.0000x reference)
#include <cuda_runtime.h>

typedef unsigned long long ull;

#define B_     128
#define QN     16
#define LN     2048
#define EMB_   128
#define KN     11
#define TPB    512
#define NPASS  4               // 4 passes x 512 docs (1 doc per thread)

// ---------------- packed f32x2 helpers ----------------
__device__ __forceinline__ void fma2(ull& d, ull a, ull b) {
    asm("fma.rn.f32x2 %0, %1, %2, %0;" : "+l"(d) : "l"(a), "l"(b));
}
__device__ __forceinline__ ull add2(ull a, ull b) {
    ull r; asm("add.rn.f32x2 %0, %1, %2;" : "=l"(r) : "l"(a), "l"(b)); return r;
}
__device__ __forceinline__ ull mul2(ull a, ull b) {
    ull r; asm("mul.rn.f32x2 %0, %1, %2;" : "=l"(r) : "l"(a), "l"(b)); return r;
}
__device__ __forceinline__ ull pack2(float lo, float hi) {
    ull r; asm("mov.b64 %0, {%1, %2};" : "=l"(r) : "f"(lo), "f"(hi)); return r;
}
__device__ __forceinline__ float2 unpack2(ull v) {
    float2 r; asm("mov.b64 {%0, %1}, %2;" : "=f"(r.x), "=f"(r.y) : "l"(v)); return r;
}
__device__ __forceinline__ float ex2a(float x) {
    float r; asm("ex2.approx.f32 %0, %1;" : "=f"(r) : "f"(x)); return r;
}
__device__ __forceinline__ float lg2a(float x) {
    float r; asm("lg2.approx.f32 %0, %1;" : "=f"(r) : "f"(x)); return r;
}

extern "C" __global__ void __launch_bounds__(TPB, 1)
knrm_fused(const int* __restrict__ queries,
           const int* __restrict__ docs,
           const float* __restrict__ emb,
           const float* __restrict__ W,
           const float* __restrict__ bias,
           float* __restrict__ out)
{
    __shared__ __align__(16) float qsT[EMB_ * QN];   // 8 KB, transposed [e][q]
    __shared__ __align__(16) float sims[QN * TPB];   // 32 KB, [q][512]
    __shared__ float nsq[QN];
    __shared__ float parts[QN];

    const int b    = blockIdx.x;
    const int tid  = threadIdx.x;
    const int lane = tid & 31;
    const int w    = tid >> 5;                 // warp id == query id for RBF

    // Prefetch all 4 doc ids (independent LDGs in flight early).
    int gid[NPASS];
    #pragma unroll
    for (int p = 0; p < NPASS; ++p)
        gid[p] = docs[b * LN + p * TPB + tid];

    // ---------- stage 1: gather + normalize queries into transposed smem ----------
    if (tid < QN) nsq[tid] = 0.0f;
    __syncthreads();
    {
        const int q1 = tid & 15;               // query
        const int c1 = tid >> 4;               // 4-float chunk (0..31)
        const int qi = queries[b * QN + q1];
        float4 v = *(const float4*)(emb + (size_t)qi * EMB_ + c1 * 4);
        float ssq = v.x*v.x + v.y*v.y + v.z*v.z + v.w*v.w;
        ssq += __shfl_xor_sync(0xffffffffu, ssq, 16);
        if (lane < 16) atomicAdd(&nsq[q1], ssq);
        __syncthreads();
        float n  = nsq[q1];
        float rn = (n > 0.0f) ? rsqrtf(n) : 0.0f;   // padding row -> sim = 0
        qsT[(c1*4+0)*QN + q1] = v.x * rn;
        qsT[(c1*4+1)*QN + q1] = v.y * rn;
        qsT[(c1*4+2)*QN + q1] = v.z * rn;
        qsT[(c1*4+3)*QN + q1] = v.w * rn;
    }
    __syncthreads();

    ull pk2[KN];
    #pragma unroll
    for (int k = 0; k < KN; ++k) pk2[k] = 0ull;
    const ull ONE2 = pack2(1.0f, 1.0f);
    const ull MP2  = pack2(-0.2f, -0.2f);
    const ull C2   = pack2(-72.13475204f, -72.13475204f); // -50 * log2(e)

    for (int pass = 0; pass < NPASS; ++pass) {
        // ---------- dot: 1 doc x 16 queries, packed accumulators ----------
        const float4* r0 = (const float4*)(emb + (size_t)gid[pass] * EMB_);
        ull acc[8], ss2 = 0ull;
        #pragma unroll
        for (int i = 0; i < 8; ++i) acc[i] = 0ull;

        #pragma unroll 4
        for (int eb = 0; eb < EMB_ / 4; ++eb) {
            float4 av = __ldg(r0 + eb);
            ull p01 = pack2(av.x, av.y);
            ull p23 = pack2(av.z, av.w);
            fma2(ss2, p01, p01);
            fma2(ss2, p23, p23);
            #pragma unroll
            for (int j = 0; j < 4; ++j) {
                float x = (j==0)?av.x:(j==1)?av.y:(j==2)?av.z:av.w;
                ull A = pack2(x, x);
                const ulonglong2* qrow = (const ulonglong2*)(qsT + (eb*4 + j)*QN);
                ulonglong2 qa = qrow[0];
                ulonglong2 qb = qrow[1];
                ulonglong2 qc = qrow[2];
                ulonglong2 qd = qrow[3];
                fma2(acc[0], A, qa.x); fma2(acc[1], A, qa.y);
                fma2(acc[2], A, qb.x); fma2(acc[3], A, qb.y);
                fma2(acc[4], A, qc.x); fma2(acc[5], A, qc.y);
                fma2(acc[6], A, qd.x); fma2(acc[7], A, qd.y);
            }
        }

        float2 nn = unpack2(ss2);
        float n  = nn.x + nn.y;
        float rd = (n > 0.0f) ? rsqrtf(n) : 0.0f;   // padding doc -> sim = 0

        __syncthreads();   // previous pass's RBF readers are done with sims
        #pragma unroll
        for (int qp = 0; qp < 8; ++qp) {
            float2 f = unpack2(acc[qp]);
            sims[(2*qp  ) * TPB + tid] = f.x * rd;
            sims[(2*qp+1) * TPB + tid] = f.y * rd;
        }
        __syncthreads();

        // ---------- RBF pooling: warp w owns query w, 512 sims, packed pairs ----------
        #pragma unroll
        for (int c = 0; c < 8; ++c) {
            float s0 = sims[w * TPB + lane + 64*c];
            float s1 = sims[w * TPB + lane + 64*c + 32];
            ull dd = add2(pack2(s0, s1), ONE2);       // d = sim - mu0, mu0 = -1
            #pragma unroll
            for (int k = 0; k < KN; ++k) {
                ull m = mul2(dd, dd);
                ull t = mul2(m, C2);                  // -50/ln2 * d^2
                float2 tf = unpack2(t);
                pk2[k] = add2(pk2[k], pack2(ex2a(tf.x), ex2a(tf.y)));
                dd = add2(dd, MP2);                   // next center: mu += 0.2
            }
        }
        // no barrier here: next pass's dot overlaps trailing RBF of slower warps
    }

    // ---------- epilogue: per-warp (per-query) reduce, log, W, sigmoid ----------
    float part = 0.0f;
    #pragma unroll
    for (int k = 0; k < KN; ++k) {
        float2 h = unpack2(pk2[k]);
        float v = h.x + h.y;
        v += __shfl_xor_sync(0xffffffffu, v, 16);
        v += __shfl_xor_sync(0xffffffffu, v, 8);
        v += __shfl_xor_sync(0xffffffffu, v, 4);
        v += __shfl_xor_sync(0xffffffffu, v, 2);
        v += __shfl_xor_sync(0xffffffffu, v, 1);
        part += __ldg(W + k) * (lg2a(v) * 0.6931471805599453f);
    }
    if (lane == 0) parts[w] = part;
    __syncthreads();
    if (tid == 0) {
        float s = __ldg(bias);
        #pragma unroll
        for (int i = 0; i < QN; ++i) s += parts[i];
        out[b] = 1.0f / (1.0f + __expf(-s));
    }
}

extern "C" void kernel_launch(void* const* d_in, const int* in_sizes, int n_in,
                              void* d_out, int out_size)
{
    const int*   queries = (const int*)d_in[0];
    const int*   docs    = (const int*)d_in[1];
    const float* emb     = (const float*)d_in[2];
    const float* W       = (const float*)d_in[3];
    const float* bias    = (const float*)d_in[4];
    float*       out     = (float*)d_out;

    knrm_fused<<<B_, TPB>>>(queries, docs, emb, W, bias, out);
}

// round 5
// speedup vs baseline: 1.0105x; 1.0105x over previous
#include <cuda_runtime.h>

typedef unsigned long long ull;

#define B_     128
#define QN     16
#define LN     2048
#define EMB_   128
#define KN     11
#define TPB    512
#define NPASS  4               // 4 passes x 512 docs (1 doc per thread)

// ---------------- packed f32x2 helpers ----------------
__device__ __forceinline__ void fma2(ull& d, ull a, ull b) {
    asm("fma.rn.f32x2 %0, %1, %2, %0;" : "+l"(d) : "l"(a), "l"(b));
}
__device__ __forceinline__ ull add2(ull a, ull b) {
    ull r; asm("add.rn.f32x2 %0, %1, %2;" : "=l"(r) : "l"(a), "l"(b)); return r;
}
__device__ __forceinline__ ull mul2(ull a, ull b) {
    ull r; asm("mul.rn.f32x2 %0, %1, %2;" : "=l"(r) : "l"(a), "l"(b)); return r;
}
__device__ __forceinline__ ull pack2(float lo, float hi) {
    ull r; asm("mov.b64 %0, {%1, %2};" : "=l"(r) : "f"(lo), "f"(hi)); return r;
}
__device__ __forceinline__ float2 unpack2(ull v) {
    float2 r; asm("mov.b64 {%0, %1}, %2;" : "=f"(r.x), "=f"(r.y) : "l"(v)); return r;
}
__device__ __forceinline__ float ex2a(float x) {
    float r; asm("ex2.approx.f32 %0, %1;" : "=f"(r) : "f"(x)); return r;
}
__device__ __forceinline__ float lg2a(float x) {
    float r; asm("lg2.approx.f32 %0, %1;" : "=f"(r) : "f"(x)); return r;
}

extern "C" __global__ void __launch_bounds__(TPB, 1)
knrm_fused(const int* __restrict__ queries,
           const int* __restrict__ docs,
           const float* __restrict__ emb,
           const float* __restrict__ W,
           const float* __restrict__ bias,
           float* __restrict__ out)
{
    __shared__ __align__(16) float qsT[EMB_ * QN];   // 8 KB, transposed [e][q]
    __shared__ __align__(16) float sims[QN * TPB];   // 32 KB, [q][512]
    __shared__ float nsq[QN];
    __shared__ float parts[QN];

    const int b    = blockIdx.x;
    const int tid  = threadIdx.x;
    const int lane = tid & 31;
    const int w    = tid >> 5;                 // warp id == query id for RBF

    // Prefetch all 4 doc ids (independent LDGs in flight early).
    int gid[NPASS];
    #pragma unroll
    for (int p = 0; p < NPASS; ++p)
        gid[p] = docs[b * LN + p * TPB + tid];

    // ---------- stage 1: gather + normalize queries into transposed smem ----------
    if (tid < QN) nsq[tid] = 0.0f;
    __syncthreads();
    {
        const int q1 = tid & 15;               // query
        const int c1 = tid >> 4;               // 4-float chunk (0..31)
        const int qi = queries[b * QN + q1];
        float4 v = *(const float4*)(emb + (size_t)qi * EMB_ + c1 * 4);
        float ssq = v.x*v.x + v.y*v.y + v.z*v.z + v.w*v.w;
        ssq += __shfl_xor_sync(0xffffffffu, ssq, 16);
        if (lane < 16) atomicAdd(&nsq[q1], ssq);
        __syncthreads();
        float n  = nsq[q1];
        float rn = (n > 0.0f) ? rsqrtf(n) : 0.0f;   // padding row -> sim = 0
        qsT[(c1*4+0)*QN + q1] = v.x * rn;
        qsT[(c1*4+1)*QN + q1] = v.y * rn;
        qsT[(c1*4+2)*QN + q1] = v.z * rn;
        qsT[(c1*4+3)*QN + q1] = v.w * rn;
    }
    __syncthreads();

    ull pk2[KN];
    #pragma unroll
    for (int k = 0; k < KN; ++k) pk2[k] = 0ull;
    const ull ONE2 = pack2(1.0f, 1.0f);
    const ull MP2  = pack2(-0.2f, -0.2f);
    const ull C2   = pack2(-72.13475204f, -72.13475204f); // -50 * log2(e)

    for (int pass = 0; pass < NPASS; ++pass) {
        // ---------- dot: 1 doc x 16 queries, packed accumulators ----------
        const float4* r0 = (const float4*)(emb + (size_t)gid[pass] * EMB_);
        ull acc[8], ss2 = 0ull;
        #pragma unroll
        for (int i = 0; i < 8; ++i) acc[i] = 0ull;

        #pragma unroll 4
        for (int eb = 0; eb < EMB_ / 4; ++eb) {
            float4 av = __ldg(r0 + eb);
            ull p01 = pack2(av.x, av.y);
            ull p23 = pack2(av.z, av.w);
            fma2(ss2, p01, p01);
            fma2(ss2, p23, p23);
            #pragma unroll
            for (int j = 0; j < 4; ++j) {
                float x = (j==0)?av.x:(j==1)?av.y:(j==2)?av.z:av.w;
                ull A = pack2(x, x);
                const ulonglong2* qrow = (const ulonglong2*)(qsT + (eb*4 + j)*QN);
                ulonglong2 qa = qrow[0];
                ulonglong2 qb = qrow[1];
                ulonglong2 qc = qrow[2];
                ulonglong2 qd = qrow[3];
                fma2(acc[0], A, qa.x); fma2(acc[1], A, qa.y);
                fma2(acc[2], A, qb.x); fma2(acc[3], A, qb.y);
                fma2(acc[4], A, qc.x); fma2(acc[5], A, qc.y);
                fma2(acc[6], A, qd.x); fma2(acc[7], A, qd.y);
            }
        }

        float2 nn = unpack2(ss2);
        float n  = nn.x + nn.y;
        float rd = (n > 0.0f) ? rsqrtf(n) : 0.0f;   // padding doc -> sim = 0

        __syncthreads();   // previous pass's RBF readers are done with sims
        #pragma unroll
        for (int qp = 0; qp < 8; ++qp) {
            float2 f = unpack2(acc[qp]);
            sims[(2*qp  ) * TPB + tid] = f.x * rd;
            sims[(2*qp+1) * TPB + tid] = f.y * rd;
        }
        __syncthreads();

        // ---------- RBF pooling: warp w owns query w, 512 sims, packed pairs ----------
        #pragma unroll
        for (int c = 0; c < 8; ++c) {
            float s0 = sims[w * TPB + lane + 64*c];
            float s1 = sims[w * TPB + lane + 64*c + 32];
            ull dd = add2(pack2(s0, s1), ONE2);       // d = sim - mu0, mu0 = -1
            #pragma unroll
            for (int k = 0; k < KN; ++k) {
                ull m = mul2(dd, dd);
                ull t = mul2(m, C2);                  // -50/ln2 * d^2
                float2 tf = unpack2(t);
                pk2[k] = add2(pk2[k], pack2(ex2a(tf.x), ex2a(tf.y)));
                dd = add2(dd, MP2);                   // next center: mu += 0.2
            }
        }
        // no barrier here: next pass's dot overlaps trailing RBF of slower warps
    }

    // ---------- epilogue: per-warp (per-query) reduce, log, W, sigmoid ----------
    float part = 0.0f;
    #pragma unroll
    for (int k = 0; k < KN; ++k) {
        float2 h = unpack2(pk2[k]);
        float v = h.x + h.y;
        v += __shfl_xor_sync(0xffffffffu, v, 16);
        v += __shfl_xor_sync(0xffffffffu, v, 8);
        v += __shfl_xor_sync(0xffffffffu, v, 4);
        v += __shfl_xor_sync(0xffffffffu, v, 2);
        v += __shfl_xor_sync(0xffffffffu, v, 1);
        part += __ldg(W + k) * (lg2a(v) * 0.6931471805599453f);
    }
    if (lane == 0) parts[w] = part;
    __syncthreads();
    if (tid == 0) {
        float s = __ldg(bias);
        #pragma unroll
        for (int i = 0; i < QN; ++i) s += parts[i];
        out[b] = 1.0f / (1.0f + __expf(-s));
    }
}

extern "C" void kernel_launch(void* const* d_in, const int* in_sizes, int n_in,
                              void* d_out, int out_size)
{
    const int*   queries = (const int*)d_in[0];
    const int*   docs    = (const int*)d_in[1];
    const float* emb     = (const float*)d_in[2];
    const float* W       = (const float*)d_in[3];
    const float* bias    = (const float*)d_in[4];
    float*       out     = (float*)d_out;

    knrm_fused<<<B_, TPB>>>(queries, docs, emb, W, bias, out);
}

// round 6
// speedup vs baseline: 1.3010x; 1.2875x over previous
#include <cuda_runtime.h>

typedef unsigned long long ull;

#define B_     128
#define QN     16
#define LN     2048
#define EMB_   128
#define KN     11
#define TPB    512
#define DPP    1024            // docs per pass (512 threads x 2 docs)
#define NC     8               // e-chunks per pass
#define EC     16              // e values per chunk
#define STG    (DPP*EC)        // words per stage buffer (16384 = 64KB)

// ---------------- packed f32x2 helpers ----------------
__device__ __forceinline__ void fma2(ull& d, ull a, ull b) {
    asm("fma.rn.f32x2 %0, %1, %2, %0;" : "+l"(d) : "l"(a), "l"(b));
}
__device__ __forceinline__ ull add2(ull a, ull b) {
    ull r; asm("add.rn.f32x2 %0, %1, %2;" : "=l"(r) : "l"(a), "l"(b)); return r;
}
__device__ __forceinline__ ull mul2(ull a, ull b) {
    ull r; asm("mul.rn.f32x2 %0, %1, %2;" : "=l"(r) : "l"(a), "l"(b)); return r;
}
__device__ __forceinline__ ull pack2(float lo, float hi) {
    ull r; asm("mov.b64 %0, {%1, %2};" : "=l"(r) : "f"(lo), "f"(hi)); return r;
}
__device__ __forceinline__ float2 unpack2(ull v) {
    float2 r; asm("mov.b64 {%0, %1}, %2;" : "=f"(r.x), "=f"(r.y) : "l"(v)); return r;
}
__device__ __forceinline__ float ex2a(float x) {
    float r; asm("ex2.approx.f32 %0, %1;" : "=f"(r) : "f"(x)); return r;
}
__device__ __forceinline__ float lg2a(float x) {
    float r; asm("lg2.approx.f32 %0, %1;" : "=f"(r) : "f"(x)); return r;
}

// ---------------- cp.async (LDGSTS) helpers ----------------
__device__ __forceinline__ unsigned smaddr(const void* p) {
    unsigned r;
    asm("{ .reg .u64 t; cvta.to.shared.u64 t, %1; cvt.u32.u64 %0, t; }"
        : "=r"(r) : "l"(p));
    return r;
}
__device__ __forceinline__ void cp16(unsigned dst, const void* src) {
    asm volatile("cp.async.ca.shared.global [%0], [%1], 16;" :: "r"(dst), "l"(src));
}
__device__ __forceinline__ void cp_commit() { asm volatile("cp.async.commit_group;"); }
__device__ __forceinline__ void cp_wait1()  { asm volatile("cp.async.wait_group 1;"); }
__device__ __forceinline__ void cp_wait0()  { asm volatile("cp.async.wait_group 0;"); }

// word offset of (doc, quarter) in a stage buffer, XOR-swizzled for bank spread
__device__ __forceinline__ int sw_off(int doc, int q) {
    return doc * EC + ((q ^ ((doc >> 1) & 3)) << 2);
}

// RBF pooling over 2 sims (packed): 11 centers via incremental mu += 0.2
#define RBF_ITER(it) do {                                                      \
    float s0 = sims[w*DPP + lane + 64*(it)];                                   \
    float s1 = sims[w*DPP + lane + 64*(it) + 32];                              \
    ull dd = add2(pack2(s0, s1), ONE2);                                        \
    _Pragma("unroll")                                                          \
    for (int k = 0; k < KN; ++k) {                                             \
        ull m = mul2(dd, dd);                                                  \
        ull t = mul2(m, C2);                                                   \
        float2 tf = unpack2(t);                                                \
        pk2[k] = add2(pk2[k], pack2(ex2a(tf.x), ex2a(tf.y)));                  \
        dd = add2(dd, MP2);                                                    \
    } } while (0)

extern "C" __global__ void __launch_bounds__(TPB, 1)
knrm_fused(const int* __restrict__ queries,
           const int* __restrict__ docs,
           const float* __restrict__ emb,
           const float* __restrict__ W,
           const float* __restrict__ bias,
           float* __restrict__ out)
{
    extern __shared__ __align__(16) float sm[];
    float* qsT   = sm;                          // [128][16]    8 KB
    float* sims  = sm + EMB_*QN;                // [16][1024]  64 KB
    float* stage = sims + QN*DPP;               // 2 x [1024][16] 128 KB
    float* nsq   = stage + 2*STG;               // [16]
    float* parts = nsq + QN;                    // [16]

    const int b    = blockIdx.x;
    const int tid  = threadIdx.x;
    const int lane = tid & 31;
    const int w    = tid >> 5;                  // warp id == query id for RBF

    const unsigned stage_u32 = smaddr(stage);
    const int d0 = tid;                         // this thread's 2 docs (slots in pass)
    const int d1 = tid + TPB;

    // ---------- stage 1: gather + normalize queries into transposed smem ----------
    if (tid < QN) nsq[tid] = 0.0f;
    __syncthreads();
    {
        const int q1 = tid & 15;
        const int c1 = tid >> 4;                // 4-float chunk (0..31)
        const int qi = queries[b*QN + q1];
        float4 v = *(const float4*)(emb + (size_t)qi*EMB_ + c1*4);
        float ssq = v.x*v.x + v.y*v.y + v.z*v.z + v.w*v.w;
        ssq += __shfl_xor_sync(0xffffffffu, ssq, 16);
        if (lane < 16) atomicAdd(&nsq[q1], ssq);
        __syncthreads();
        float n  = nsq[q1];
        float rn = (n > 0.0f) ? rsqrtf(n) : 0.0f;   // padding row -> sim = 0
        qsT[(c1*4+0)*QN + q1] = v.x*rn;
        qsT[(c1*4+1)*QN + q1] = v.y*rn;
        qsT[(c1*4+2)*QN + q1] = v.z*rn;
        qsT[(c1*4+3)*QN + q1] = v.w*rn;
    }
    __syncthreads();

    ull pk2[KN];
    #pragma unroll
    for (int k = 0; k < KN; ++k) pk2[k] = 0ull;
    const ull ONE2 = pack2(1.0f, 1.0f);
    const ull MP2  = pack2(-0.2f, -0.2f);
    const ull C2   = pack2(-72.13475204f, -72.13475204f); // -50 * log2(e)

    #pragma unroll 1
    for (int pass = 0; pass < 2; ++pass) {
        // doc ids this thread stages: slots r*128 + tid/4, quarter tid%4
        const float* gsrc[NC];
        {
            const int q4 = tid & 3;
            #pragma unroll
            for (int r = 0; r < NC; ++r) {
                int gid = docs[b*LN + pass*DPP + r*128 + (tid >> 2)];
                gsrc[r] = emb + (size_t)gid*EMB_ + q4*4;
            }
        }
        // issue chunk 0 into buffer 0
        {
            const int q4 = tid & 3;
            #pragma unroll
            for (int r = 0; r < NC; ++r)
                cp16(stage_u32 + 4u*sw_off(r*128 + (tid >> 2), q4), gsrc[r]);
            cp_commit();
        }

        ull acc0[8], acc1[8], ss2 = 0ull;
        #pragma unroll
        for (int i = 0; i < 8; ++i) { acc0[i] = 0ull; acc1[i] = 0ull; }

        #pragma unroll 1
        for (int c = 0; c < NC; ++c) {
            if (c + 1 < NC) {
                const int q4  = tid & 3;
                const int buf = (c + 1) & 1;
                #pragma unroll
                for (int r = 0; r < NC; ++r)
                    cp16(stage_u32 + 4u*(buf*STG + sw_off(r*128 + (tid >> 2), q4)),
                         gsrc[r] + (c + 1)*EC);
                cp_commit();
                cp_wait1();
            } else {
                cp_wait0();
            }
            __syncthreads();

            // ---------- compute chunk c: 16 e's, 2 docs x 16 queries ----------
            const float* sbuf = stage + (c & 1)*STG;
            #pragma unroll
            for (int j = 0; j < 4; ++j) {
                float4 a0 = *(const float4*)(sbuf + sw_off(d0, j));
                float4 a1 = *(const float4*)(sbuf + sw_off(d1, j));
                #pragma unroll
                for (int jj = 0; jj < 4; ++jj) {
                    float x0 = (jj==0)?a0.x:(jj==1)?a0.y:(jj==2)?a0.z:a0.w;
                    float x1 = (jj==0)?a1.x:(jj==1)?a1.y:(jj==2)?a1.z:a1.w;
                    ull A0 = pack2(x0, x0);
                    ull A1 = pack2(x1, x1);
                    ull SS = pack2(x0, x1);
                    fma2(ss2, SS, SS);
                    const ulonglong2* qrow =
                        (const ulonglong2*)(qsT + (c*EC + j*4 + jj)*QN);
                    ulonglong2 qa = qrow[0];
                    ulonglong2 qb = qrow[1];
                    fma2(acc0[0], A0, qa.x); fma2(acc0[1], A0, qa.y);
                    fma2(acc0[2], A0, qb.x); fma2(acc0[3], A0, qb.y);
                    fma2(acc1[0], A1, qa.x); fma2(acc1[1], A1, qa.y);
                    fma2(acc1[2], A1, qb.x); fma2(acc1[3], A1, qb.y);
                    ulonglong2 qc = qrow[2];
                    ulonglong2 qd = qrow[3];
                    fma2(acc0[4], A0, qc.x); fma2(acc0[5], A0, qc.y);
                    fma2(acc0[6], A0, qd.x); fma2(acc0[7], A0, qd.y);
                    fma2(acc1[4], A1, qc.x); fma2(acc1[5], A1, qc.y);
                    fma2(acc1[6], A1, qd.x); fma2(acc1[7], A1, qd.y);
                }
            }

            // RBF of pass-0 sims interleaved into pass-1 dot (sims not yet rewritten)
            if (pass == 1) {
                RBF_ITER(2*c);
                RBF_ITER(2*c + 1);
            }
            __syncthreads();
        }

        // ---------- norms + write sims (transpose to [q][doc]) ----------
        {
            float2 nn = unpack2(ss2);
            float rd0 = (nn.x > 0.0f) ? rsqrtf(nn.x) : 0.0f;  // padding doc -> sim 0
            float rd1 = (nn.y > 0.0f) ? rsqrtf(nn.y) : 0.0f;
            #pragma unroll
            for (int qp = 0; qp < 8; ++qp) {
                float2 f0 = unpack2(acc0[qp]);
                float2 f1 = unpack2(acc1[qp]);
                sims[(2*qp  )*DPP + d0] = f0.x * rd0;
                sims[(2*qp+1)*DPP + d0] = f0.y * rd0;
                sims[(2*qp  )*DPP + d1] = f1.x * rd1;
                sims[(2*qp+1)*DPP + d1] = f1.y * rd1;
            }
        }
        __syncthreads();
    }

    // ---------- RBF over pass-1 sims (exposed tail) ----------
    #pragma unroll 2
    for (int it = 0; it < 16; ++it) RBF_ITER(it);

    // ---------- epilogue: per-warp (per-query) reduce, log, W, sigmoid ----------
    float part = 0.0f;
    #pragma unroll
    for (int k = 0; k < KN; ++k) {
        float2 h = unpack2(pk2[k]);
        float v = h.x + h.y;
        v += __shfl_xor_sync(0xffffffffu, v, 16);
        v += __shfl_xor_sync(0xffffffffu, v, 8);
        v += __shfl_xor_sync(0xffffffffu, v, 4);
        v += __shfl_xor_sync(0xffffffffu, v, 2);
        v += __shfl_xor_sync(0xffffffffu, v, 1);
        part += __ldg(W + k) * (lg2a(v) * 0.6931471805599453f);
    }
    if (lane == 0) parts[w] = part;
    __syncthreads();
    if (tid == 0) {
        float s = __ldg(bias);
        #pragma unroll
        for (int i = 0; i < QN; ++i) s += parts[i];
        out[b] = 1.0f / (1.0f + __expf(-s));
    }
}

extern "C" void kernel_launch(void* const* d_in, const int* in_sizes, int n_in,
                              void* d_out, int out_size)
{
    const int*   queries = (const int*)d_in[0];
    const int*   docs    = (const int*)d_in[1];
    const float* emb     = (const float*)d_in[2];
    const float* W       = (const float*)d_in[3];
    const float* bias    = (const float*)d_in[4];
    float*       out     = (float*)d_out;

    const int smem = (EMB_*QN + QN*DPP + 2*STG + 2*QN) * (int)sizeof(float); // ~205 KB
    cudaFuncSetAttribute(knrm_fused, cudaFuncAttributeMaxDynamicSharedMemorySize, smem);

    knrm_fused<<<B_, TPB, smem>>>(queries, docs, emb, W, bias, out);
}